// round 5
// baseline (speedup 1.0000x reference)
#include <cuda_runtime.h>
#include <math.h>

#define B 128
#define T 200
#define V 50257
#define H 256
#define EDIM 128
#define TWOH 512
#define GIN 640           // 2H + E, selective_read first then embedding
#define G3 768            // 3H
#define MAXOOV 50
#define OV (V + MAXOOV)   // 50307

static const size_t OFF_H = (size_t)B * OV;              // decode_hidden offset in out
static const size_t OFF_S = (size_t)B * OV + (size_t)B * H; // selective_read_new offset

// ---------------- device scratch (no allocation allowed) ----------------
__device__ float g_score_g[(size_t)B * V];     // 25.7 MB
__device__ float g_encproj[(size_t)B * T * H]; // 26.2 MB
__device__ float g_score_c[B * T];
__device__ float g_gin[B * GIN];
__device__ float g_gi[B * G3];
__device__ float g_gh[B * G3];
__device__ float g_prev[B * H];
__device__ float g_hid[B * H];
__device__ float g_rmax[B];
__device__ float g_rsum[B];

// ---------------- prep: step handling + gru_in assembly ----------------
__global__ void prep_kernel(const int* __restrict__ dec, const float* __restrict__ enc,
                            const float* __restrict__ prev, const float* __restrict__ selr,
                            const int* __restrict__ stepp, const float* __restrict__ emb,
                            const float* __restrict__ Wi_w, const float* __restrict__ Wi_b,
                            float* __restrict__ pv, float* __restrict__ gin) {
    int b = blockIdx.x;
    int tid = threadIdx.x; // 512 threads
    int step = stepp ? *stepp : 1;
    __shared__ float se[TWOH];
    if (step != 0) {
        float v = selr[(size_t)b * TWOH + tid];
        gin[(size_t)b * GIN + tid] = v;
        if (tid < H) pv[b * H + tid] = prev[b * H + tid];
    } else {
        gin[(size_t)b * GIN + tid] = 0.0f;
        se[tid] = enc[((size_t)b * T + (T - 1)) * TWOH + tid];
        __syncthreads();
        if (tid < H) {
            float s = Wi_b[tid];
            #pragma unroll 8
            for (int k = 0; k < TWOH; k++) s += se[k] * Wi_w[tid * TWOH + k];
            pv[b * H + tid] = s;
        }
    }
    if (tid < EDIM) gin[(size_t)b * GIN + TWOH + tid] = emb[(size_t)dec[b] * EDIM + tid];
}

// ---------------- generic SGEMM: C[M,N] = A[M,K] @ Bt[N,K]^T + bias ----------------
// BM=128 (rows via blockIdx.y, M must be multiple of 128), BN=64, BK=32.
// act: 0 = linear, 1 = tanh
#define BM 128
#define BN 64
#define BK 32
#define TM 4
#define TN 8

__global__ void __launch_bounds__(256) sgemm_tn(const float* __restrict__ A,
                                                const float* __restrict__ Bt,
                                                const float* __restrict__ bias,
                                                float* __restrict__ C,
                                                int N, int K, int act) {
    __shared__ float As[BK][BM + 4];  // [32][132]
    __shared__ float Bs[BK][BN + 4];  // [32][68]
    int tid = threadIdx.x;
    int mg = tid & 31, ng = tid >> 5;
    int m0 = mg * TM, n0 = ng * TN;
    size_t mbase = (size_t)blockIdx.y * BM;
    int nbase = blockIdx.x * BN;

    float acc[TM][TN];
    #pragma unroll
    for (int i = 0; i < TM; i++)
        #pragma unroll
        for (int j = 0; j < TN; j++) acc[i][j] = 0.0f;

    for (int kk = 0; kk < K; kk += BK) {
        // A tile: 128 rows x 32 cols (transpose to As[k][m])
        #pragma unroll
        for (int i = tid; i < BM * (BK / 4); i += 256) {
            int row = i >> 3, c4 = i & 7;
            float4 v = *(const float4*)(A + (mbase + row) * (size_t)K + kk + c4 * 4);
            As[c4 * 4 + 0][row] = v.x;
            As[c4 * 4 + 1][row] = v.y;
            As[c4 * 4 + 2][row] = v.z;
            As[c4 * 4 + 3][row] = v.w;
        }
        // B tile: 64 n-rows x 32 cols (transpose to Bs[k][n]), guard ragged N
        #pragma unroll
        for (int i = tid; i < BN * (BK / 4); i += 256) {
            int row = i >> 3, c4 = i & 7;
            int n = nbase + row;
            float4 v = (n < N) ? *(const float4*)(Bt + (size_t)n * K + kk + c4 * 4)
                               : make_float4(0.f, 0.f, 0.f, 0.f);
            Bs[c4 * 4 + 0][row] = v.x;
            Bs[c4 * 4 + 1][row] = v.y;
            Bs[c4 * 4 + 2][row] = v.z;
            Bs[c4 * 4 + 3][row] = v.w;
        }
        __syncthreads();
        #pragma unroll 16
        for (int k = 0; k < BK; k++) {
            float a[TM], bb[TN];
            *(float4*)&a[0] = *(const float4*)&As[k][m0];
            *(float4*)&bb[0] = *(const float4*)&Bs[k][n0];
            *(float4*)&bb[4] = *(const float4*)&Bs[k][n0 + 4];
            #pragma unroll
            for (int i = 0; i < TM; i++)
                #pragma unroll
                for (int j = 0; j < TN; j++) acc[i][j] += a[i] * bb[j];
        }
        __syncthreads();
    }
    #pragma unroll
    for (int j = 0; j < TN; j++) {
        int n = nbase + n0 + j;
        if (n < N) {
            float bi = bias[n];
            #pragma unroll
            for (int i = 0; i < TM; i++) {
                float v = acc[i][j] + bi;
                if (act) v = tanhf(v);
                C[(mbase + m0 + i) * (size_t)N + n] = v;
            }
        }
    }
}

// ---------------- GRU gates ----------------
__global__ void gate_kernel(const float* __restrict__ gi, const float* __restrict__ gh,
                            const float* __restrict__ pv, float* __restrict__ hd,
                            float* __restrict__ out) {
    int b = blockIdx.x, j = threadIdx.x; // H threads
    const float* gib = gi + (size_t)b * G3;
    const float* ghb = gh + (size_t)b * G3;
    float r = 1.0f / (1.0f + expf(-(gib[j] + ghb[j])));
    float z = 1.0f / (1.0f + expf(-(gib[H + j] + ghb[H + j])));
    float n = tanhf(gib[2 * H + j] + r * ghb[2 * H + j]);
    float h = (1.0f - z) * n + z * pv[b * H + j];
    hd[b * H + j] = h;
    out[OFF_H + (size_t)b * H + j] = h;
}

// ---------------- score_c: tanh(P[bt,:] . d[b]) + mask ----------------
__global__ void scorec_kernel(const float* __restrict__ ep, const float* __restrict__ hd,
                              const int* __restrict__ idxs, float* __restrict__ sc) {
    int w = (blockIdx.x * blockDim.x + threadIdx.x) >> 5;
    int lane = threadIdx.x & 31;
    if (w >= B * T) return;
    int b = w / T;
    const float* P = ep + (size_t)w * H;
    const float* D = hd + (size_t)b * H;
    float s = 0.0f;
    #pragma unroll
    for (int k = lane; k < H; k += 32) s += P[k] * D[k];
    #pragma unroll
    for (int o = 16; o > 0; o >>= 1) s += __shfl_xor_sync(0xffffffffu, s, o);
    if (lane == 0) {
        float v = tanhf(s);
        if (idxs[w] == 0) v -= 10000.0f;
        sc[w] = v;
    }
}

// ---------------- joint softmax row reduce (online max/sum) ----------------
__global__ void rowreduce_kernel(const float* __restrict__ sg, const float* __restrict__ sc,
                                 float* __restrict__ rmax, float* __restrict__ rsum) {
    int b = blockIdx.x, tid = threadIdx.x; // 256 threads
    const int total = V + T;
    float m = -INFINITY, s = 0.0f;
    for (int j = tid; j < total; j += 256) {
        float v = (j < V) ? sg[(size_t)b * V + j] : sc[b * T + (j - V)];
        if (v > m) { s = s * expf(m - v) + 1.0f; m = v; }
        else       { s += expf(v - m); }
    }
    __shared__ float sm[256], ss[256];
    sm[tid] = m; ss[tid] = s;
    __syncthreads();
    for (int st = 128; st > 0; st >>= 1) {
        if (tid < st) {
            float m2 = sm[tid + st], s2 = ss[tid + st];
            float M = fmaxf(sm[tid], m2);
            ss[tid] = ss[tid] * expf(sm[tid] - M) + s2 * expf(m2 - M);
            sm[tid] = M;
        }
        __syncthreads();
    }
    if (tid == 0) { rmax[b] = sm[0]; rsum[b] = ss[0]; }
}

// ---------------- prob_out base (generation probs + OOV constant) ----------------
__global__ void prob_kernel(const float* __restrict__ sg, const float* __restrict__ rmax,
                            const float* __restrict__ rsum, float* __restrict__ out) {
    int b = blockIdx.y;
    int j = blockIdx.x * 256 + threadIdx.x;
    if (j >= OV) return;
    float m = rmax[b], inv = 1.0f / rsum[b];
    out[(size_t)b * OV + j] = (j < V) ? expf(sg[(size_t)b * V + j] - m) * inv : 0.0001f;
}

// ---------------- scatter copy probs ----------------
__global__ void scatter_kernel(const float* __restrict__ sc, const int* __restrict__ idxs,
                               const float* __restrict__ rmax, const float* __restrict__ rsum,
                               float* __restrict__ out) {
    int i = blockIdx.x * 256 + threadIdx.x;
    if (i >= B * T) return;
    int b = i / T;
    float p = expf(sc[i] - rmax[b]) / rsum[b];
    atomicAdd(&out[(size_t)b * OV + idxs[i]], p);
}

// ---------------- selective read (matched positions only) ----------------
__global__ void selread_kernel(const float* __restrict__ sc, const int* __restrict__ idxs,
                               const int* __restrict__ dec, const float* __restrict__ enc,
                               const float* __restrict__ rmax, const float* __restrict__ rsum,
                               float* __restrict__ out) {
    int b = blockIdx.x, tid = threadIdx.x; // 256 threads
    __shared__ int s_cnt;
    __shared__ int s_ts[T];
    __shared__ float s_w[T];
    if (tid == 0) {
        int d = dec[b];
        int cnt = 0;
        float m = rmax[b], inv = 1.0f / rsum[b];
        for (int t = 0; t < T; t++) {
            if (idxs[b * T + t] == d) {
                s_ts[cnt] = t;
                s_w[cnt] = expf(sc[b * T + t] - m) * inv;
                cnt++;
            }
        }
        s_cnt = cnt;
    }
    __syncthreads();
    int cnt = s_cnt;
    float scale = (cnt > 1) ? (1.0f / (float)cnt) : 1.0f;
    for (int e = tid; e < TWOH; e += 256) {
        float acc = 0.0f;
        for (int i = 0; i < cnt; i++)
            acc += s_w[i] * enc[((size_t)b * T + s_ts[i]) * TWOH + e];
        out[OFF_S + (size_t)b * TWOH + e] = acc * scale;
    }
}

// ---------------- launch ----------------
extern "C" void kernel_launch(void* const* d_in, const int* in_sizes, int n_in,
                              void* d_out, int out_size) {
    int o = (n_in >= 17) ? 0 : -1; // tolerate scalar `step` being dropped
    const int*   dec   = (const int*)d_in[0];
    const float* enc   = (const float*)d_in[1];
    const int*   idxs  = (const int*)d_in[2];
    const float* prev  = (const float*)d_in[3];
    const float* selr  = (const float*)d_in[4];
    const int*   stepp = (o == 0) ? (const int*)d_in[5] : nullptr;
    const float* emb   = (const float*)d_in[6 + o];
    const float* W_ih  = (const float*)d_in[7 + o];
    const float* W_hh  = (const float*)d_in[8 + o];
    const float* b_ih  = (const float*)d_in[9 + o];
    const float* b_hh  = (const float*)d_in[10 + o];
    const float* Wi_w  = (const float*)d_in[11 + o];
    const float* Wi_b  = (const float*)d_in[12 + o];
    const float* Wg_w  = (const float*)d_in[13 + o];
    const float* Wg_b  = (const float*)d_in[14 + o];
    const float* Wc_w  = (const float*)d_in[15 + o];
    const float* Wc_b  = (const float*)d_in[16 + o];
    float* out = (float*)d_out;

    float *sg, *ep, *sc, *gin, *gi, *gh, *pv, *hd, *rmax, *rsum;
    cudaGetSymbolAddress((void**)&sg,   g_score_g);
    cudaGetSymbolAddress((void**)&ep,   g_encproj);
    cudaGetSymbolAddress((void**)&sc,   g_score_c);
    cudaGetSymbolAddress((void**)&gin,  g_gin);
    cudaGetSymbolAddress((void**)&gi,   g_gi);
    cudaGetSymbolAddress((void**)&gh,   g_gh);
    cudaGetSymbolAddress((void**)&pv,   g_prev);
    cudaGetSymbolAddress((void**)&hd,   g_hid);
    cudaGetSymbolAddress((void**)&rmax, g_rmax);
    cudaGetSymbolAddress((void**)&rsum, g_rsum);

    // 1. step handling + embedding gather + gru_in assembly
    prep_kernel<<<B, 512>>>(dec, enc, prev, selr, stepp, emb, Wi_w, Wi_b, pv, gin);
    // 2. GRU input/hidden projections
    sgemm_tn<<<dim3(G3 / BN, 1), 256>>>(gin, W_ih, b_ih, gi, G3, GIN, 0);
    sgemm_tn<<<dim3(G3 / BN, 1), 256>>>(pv, W_hh, b_hh, gh, G3, H, 0);
    // 3. GRU gates -> decode_hidden (also written to output)
    gate_kernel<<<B, H>>>(gi, gh, pv, hd, out);
    // 4. generation scores: [128 x 50257] = hd @ Wg_w^T + Wg_b
    sgemm_tn<<<dim3((V + BN - 1) / BN, 1), 256>>>(hd, Wg_w, Wg_b, sg, V, H, 0);
    // 5. enc projection: [25600 x 256] = tanh(enc @ Wc_w^T + Wc_b)
    sgemm_tn<<<dim3(H / BN, (B * T) / BM), 256>>>(enc, Wc_w, Wc_b, ep, H, TWOH, 1);
    // 6. copy scores
    scorec_kernel<<<(B * T) / 8, 256>>>(ep, hd, idxs, sc);
    // 7. joint softmax statistics
    rowreduce_kernel<<<B, 256>>>(sg, sc, rmax, rsum);
    // 8. prob_out base
    prob_kernel<<<dim3((OV + 255) / 256, B), 256>>>(sg, rmax, rsum, out);
    // 9. scatter-add copy probs
    scatter_kernel<<<(B * T + 255) / 256, 256>>>(sc, idxs, rmax, rsum, out);
    // 10. selective read
    selread_kernel<<<B, 256>>>(sc, idxs, dec, enc, rmax, rsum, out);
}